// round 5
// baseline (speedup 1.0000x reference)
#include <cuda_runtime.h>

// out[b,pi,pj,h,w] = leaky_relu( (1/32) * sum_c x1[b,c,h,w] *
//                    x2_pad[b,c, h+2*pi-20, w+2*pj-20], 0.1 )
// B=4, C=32, H=32, W=1024, PATCH=21, DIL=2, PAD=20.

#define WT     128     // w-tile per block
#define SLICE  176     // slice row stride (16-bank shift -> conflict-free staging)
#define PATCH  21
#define CPH    8       // channels per pipeline stage
#define NBUF   2

__device__ __forceinline__ unsigned long long ffma2(unsigned long long a,
                                                    unsigned long long b,
                                                    unsigned long long c) {
    unsigned long long d;
    asm("fma.rn.f32x2 %0, %1, %2, %3;" : "=l"(d) : "l"(a), "l"(b), "l"(c));
    return d;
}

__device__ __forceinline__ void cp16(void* dst_smem, const void* src_gmem) {
    unsigned u = (unsigned)__cvta_generic_to_shared(dst_smem);
    asm volatile("cp.async.cg.shared.global [%0], [%1], 16;\n"
                 :: "r"(u), "l"(src_gmem));
}

extern __shared__ float smem[];

__global__ void __launch_bounds__(128, 4)
corr_kernel(const float* __restrict__ x1, const float* __restrict__ x2,
            float* __restrict__ out)
{
    const int w0   = blockIdx.x * WT;
    const int h    = blockIdx.y;
    const int b    = blockIdx.z;
    const int tid  = threadIdx.x;
    const int wid  = tid >> 5;          // 4 warps
    const int lane = tid & 31;
    const int g    = lane >> 1;         // w-group: 16 groups of 8 w's
    const int half = lane & 1;          // 0: pj 0..10, 1: pj 10..20

    // staging map: 4 lanes per slice row (8 rows), stride-4 chunk interleave
    const int sr = lane >> 2;           // row 0..7 (channel within stage)
    const int sq = lane & 3;            // chunk phase 0..3

    float* x2b = smem + wid * (NBUF * CPH * SLICE);

    const bool interior = (w0 >= 128) && (w0 <= 768);
    const int  wb = w0 - 20;

    // pi list for this warp
    int piv[6];
    int npi = 0;
    for (int pi = wid; pi < PATCH; pi += 4) piv[npi++] = pi;
    const int total = npi * 4;          // stages: 4 phases of 8 channels per pi

    // issue cp.async's for stage s (one commit group per stage)
    auto do_stage = [&](int s) {
        const int pi = piv[s >> 2];
        const int ph = s & 3;
        const int h2 = h + 2 * pi - 20;
        float* dst = x2b + (s & 1) * (CPH * SLICE) + sr * SLICE;
        if (h2 >= 0 && h2 < 32) {
            const float* src =
                x2 + ((size_t)(b * 32 + ph * CPH + sr) * 32 + h2) * 1024;
            if (interior) {
                #pragma unroll
                for (int t = 0; t < 11; t++) {
                    const int j = sq + 4 * t;
                    if (j < 42) cp16(dst + 4 * j, src + wb + 4 * j);
                }
            } else {
                #pragma unroll 4
                for (int t = 0; t < 11; t++) {
                    const int j = sq + 4 * t;
                    if (j >= 42) break;
                    const int w2 = wb + 4 * j;
                    if (w2 >= 0 && w2 <= 1020) {
                        cp16(dst + 4 * j, src + w2);
                    } else {
                        float4 v;
                        v.x = (w2     >= 0 && w2     < 1024) ? src[w2]     : 0.f;
                        v.y = (w2 + 1 >= 0 && w2 + 1 < 1024) ? src[w2 + 1] : 0.f;
                        v.z = (w2 + 2 >= 0 && w2 + 2 < 1024) ? src[w2 + 2] : 0.f;
                        v.w = (w2 + 3 >= 0 && w2 + 3 < 1024) ? src[w2 + 3] : 0.f;
                        *reinterpret_cast<float4*>(dst + 4 * j) = v;
                    }
                }
            }
        } else {
            const float4 z = make_float4(0.f, 0.f, 0.f, 0.f);
            #pragma unroll
            for (int t = 0; t < 11; t++) {
                const int j = sq + 4 * t;
                if (j < 42) *reinterpret_cast<float4*>(dst + 4 * j) = z;
            }
        }
        asm volatile("cp.async.commit_group;\n" ::: "memory");
    };

    // acc[p][q]: pj = p + 10*half, w-pair q of this lane's 8 w's
    unsigned long long acc[11][4];
    #pragma unroll
    for (int p = 0; p < 11; p++)
        #pragma unroll
        for (int q = 0; q < 4; q++) acc[p][q] = 0ull;

    // x1 read directly from global (L1-resident tile): 8 floats per lane/channel
    const float* x1g = x1 + ((size_t)b * 32 * 32 + h) * 1024 + w0 + 8 * g;
    const float sp = 0.03125f;    // 1/32
    const float sn = 0.003125f;   // 0.1/32

    do_stage(0);

    for (int s = 0; s < total; s++) {
        if (s + 1 < total) {
            do_stage(s + 1);
            asm volatile("cp.async.wait_group 1;\n" ::: "memory");
        } else {
            asm volatile("cp.async.wait_group 0;\n" ::: "memory");
        }
        __syncwarp();

        // ---- compute stage s: 8 channels ----
        const float* buf = x2b + (s & 1) * (CPH * SLICE);
        const int ph = s & 3;
        const float* x1p = x1g + (size_t)ph * CPH * 32 * 1024;
        const float* xwp = buf + 8 * g + 20 * half;

        #pragma unroll 2
        for (int c = 0; c < CPH; c++) {
            ulonglong2 X[7];
            const float* bp = xwp + c * SLICE;
            #pragma unroll
            for (int j = 0; j < 7; j++)
                X[j] = *reinterpret_cast<const ulonglong2*>(bp + 4 * j);

            const float* x1row = x1p + (size_t)c * 32 * 1024;

            #pragma unroll
            for (int qq = 0; qq < 2; qq++) {
                const ulonglong2 A =
                    *reinterpret_cast<const ulonglong2*>(x1row + 4 * qq);
                #pragma unroll
                for (int p = 0; p < 11; p++) {
                    {
                        const int k = p + 2 * qq;              // q = 2*qq
                        const unsigned long long pk = (k & 1) ? X[k >> 1].y
                                                              : X[k >> 1].x;
                        acc[p][2 * qq] = ffma2(A.x, pk, acc[p][2 * qq]);
                    }
                    {
                        const int k = p + 2 * qq + 1;          // q = 2*qq+1
                        const unsigned long long pk = (k & 1) ? X[k >> 1].y
                                                              : X[k >> 1].x;
                        acc[p][2 * qq + 1] = ffma2(A.y, pk, acc[p][2 * qq + 1]);
                    }
                }
            }
        }

        // ---- per-pi epilogue after last phase ----
        if ((s & 3) == 3) {
            const int pi = piv[s >> 2];
            #pragma unroll
            for (int p = 0; p < 11; p++) {
                if (!(half == 1 && p == 0)) {      // pj=10 duplicated by half A
                    const int pj = half ? (p + 10) : p;
                    float* op = out +
                        (((size_t)b * 441 + pi * 21 + pj) * 32 + h) * 1024 +
                        w0 + 8 * g;
                    float v[8];
                    #pragma unroll
                    for (int q = 0; q < 4; q++) {
                        float2 f = *reinterpret_cast<float2*>(&acc[p][q]);
                        v[2 * q]     = f.x * ((f.x < 0.f) ? sn : sp);
                        v[2 * q + 1] = f.y * ((f.y < 0.f) ? sn : sp);
                    }
                    *reinterpret_cast<float4*>(op) =
                        make_float4(v[0], v[1], v[2], v[3]);
                    *reinterpret_cast<float4*>(op + 4) =
                        make_float4(v[4], v[5], v[6], v[7]);
                }
                #pragma unroll
                for (int q = 0; q < 4; q++) acc[p][q] = 0ull;
            }
        }
        __syncwarp();   // buffer reads done before it is restaged
    }
}

extern "C" void kernel_launch(void* const* d_in, const int* in_sizes, int n_in,
                              void* d_out, int out_size) {
    const float* x1 = (const float*)d_in[0];
    const float* x2 = (const float*)d_in[1];
    float* out = (float*)d_out;

    const size_t smem_bytes =
        (size_t)(4 * NBUF * CPH * SLICE) * sizeof(float);   // 45056 B
    cudaFuncSetAttribute(corr_kernel,
                         cudaFuncAttributeMaxDynamicSharedMemorySize,
                         (int)smem_bytes);

    dim3 grid(1024 / WT, 32, 4);   // (w-tiles, H, B)
    corr_kernel<<<grid, 128, smem_bytes>>>(x1, x2, out);
}

// round 6
// speedup vs baseline: 1.2856x; 1.2856x over previous
#include <cuda_runtime.h>

// out[b,pi,pj,h,w] = leaky_relu( (1/32) * sum_c x1[b,c,h,w] *
//                    x2_pad[b,c, h+2*pi-20, w+2*pj-20], 0.1 )
// B=4, C=32, H=32, W=1024, PATCH=21, DIL=2, PAD=20.

#define WT     128     // w-tile per block
#define SLICE  176     // slice row stride (16-bank shift -> conflict-free)
#define PATCH  21
#define CPH    4       // channels per pipeline stage (8 phases per pi)
#define NBUF   2

__device__ __forceinline__ unsigned long long ffma2(unsigned long long a,
                                                    unsigned long long b,
                                                    unsigned long long c) {
    unsigned long long d;
    asm("fma.rn.f32x2 %0, %1, %2, %3;" : "=l"(d) : "l"(a), "l"(b), "l"(c));
    return d;
}

__device__ __forceinline__ void cp16(void* dst_smem, const void* src_gmem) {
    unsigned u = (unsigned)__cvta_generic_to_shared(dst_smem);
    asm volatile("cp.async.cg.shared.global [%0], [%1], 16;\n"
                 :: "r"(u), "l"(src_gmem));
}

extern __shared__ float smem[];

__global__ void __launch_bounds__(128, 4)
corr_kernel(const float* __restrict__ x1, const float* __restrict__ x2,
            float* __restrict__ out)
{
    const int w0   = blockIdx.x * WT;
    const int h    = blockIdx.y;
    const int b    = blockIdx.z;
    const int tid  = threadIdx.x;
    const int wid  = tid >> 5;          // 4 warps
    const int lane = tid & 31;
    const int g    = lane >> 1;         // w-group: 16 groups of 8 w's
    const int half = lane & 1;          // 0: pj 0..10, 1: pj 10..20

    // staging map: 8 lanes per slice row (4 rows), stride-8 chunk interleave
    const int sr = lane >> 3;           // row 0..3 (channel within stage)
    const int sq = lane & 7;            // chunk phase 0..7

    float* x1s = smem;                                   // [32][WT]
    float* x2b = smem + 32 * WT + wid * (NBUF * CPH * SLICE);

    // ---- stage x1 tile: 32 channels x WT floats ----
    for (int f = tid; f < 32 * (WT / 4); f += 128) {
        const int c = f >> 5;
        const int j = f & 31;
        reinterpret_cast<float4*>(x1s)[f] = *reinterpret_cast<const float4*>(
            x1 + ((size_t)(b * 32 + c) * 32 + h) * 1024 + w0 + 4 * j);
    }
    __syncthreads();

    const bool interior = (w0 >= 128) && (w0 <= 768);
    const int  wb = w0 - 20;

    const int npi   = ((PATCH - 1 - wid) >> 2) + 1;   // 6,5,5,5
    const int total = npi * 8;          // stages: 8 phases of 4 channels per pi

    // issue cp.async's for stage s (one commit group per stage)
    auto do_stage = [&](int s) {
        const int pi = wid + ((s >> 3) << 2);
        const int ph = s & 7;
        const int h2 = h + 2 * pi - 20;
        float* dst = x2b + (s & 1) * (CPH * SLICE) + sr * SLICE;
        if (h2 >= 0 && h2 < 32) {
            const float* src =
                x2 + ((size_t)(b * 32 + ph * CPH + sr) * 32 + h2) * 1024;
            if (interior) {
                #pragma unroll
                for (int t = 0; t < 6; t++) {
                    const int j = sq + 8 * t;
                    if (j < 42) cp16(dst + 4 * j, src + wb + 4 * j);
                }
            } else {
                #pragma unroll
                for (int t = 0; t < 6; t++) {
                    const int j = sq + 8 * t;
                    if (j >= 42) break;
                    const int w2 = wb + 4 * j;
                    if (w2 >= 0 && w2 <= 1020) {
                        cp16(dst + 4 * j, src + w2);
                    } else {
                        float4 v;
                        v.x = (w2     >= 0 && w2     < 1024) ? src[w2]     : 0.f;
                        v.y = (w2 + 1 >= 0 && w2 + 1 < 1024) ? src[w2 + 1] : 0.f;
                        v.z = (w2 + 2 >= 0 && w2 + 2 < 1024) ? src[w2 + 2] : 0.f;
                        v.w = (w2 + 3 >= 0 && w2 + 3 < 1024) ? src[w2 + 3] : 0.f;
                        *reinterpret_cast<float4*>(dst + 4 * j) = v;
                    }
                }
            }
        } else {
            const float4 z = make_float4(0.f, 0.f, 0.f, 0.f);
            #pragma unroll
            for (int t = 0; t < 6; t++) {
                const int j = sq + 8 * t;
                if (j < 42) *reinterpret_cast<float4*>(dst + 4 * j) = z;
            }
        }
        asm volatile("cp.async.commit_group;\n" ::: "memory");
    };

    // acc[p][q]: pj = p + 10*half, w-pair q of this lane's 8 w's
    unsigned long long acc[11][4];
    #pragma unroll
    for (int p = 0; p < 11; p++)
        #pragma unroll
        for (int q = 0; q < 4; q++) acc[p][q] = 0ull;

    const float* x1base = x1s + 8 * g;
    const float sp = 0.03125f;    // 1/32
    const float sn = 0.003125f;   // 0.1/32

    do_stage(0);

    for (int s = 0; s < total; s++) {
        if (s + 1 < total) {
            do_stage(s + 1);
            asm volatile("cp.async.wait_group 1;\n" ::: "memory");
        } else {
            asm volatile("cp.async.wait_group 0;\n" ::: "memory");
        }
        __syncwarp();

        // ---- compute stage s: 4 channels ----
        const float* buf = x2b + (s & 1) * (CPH * SLICE);
        const int ph = s & 7;
        const float* x1p = x1base + ph * CPH * WT;
        const float* xwp = buf + 8 * g + 20 * half;

        #pragma unroll 2
        for (int c = 0; c < CPH; c++) {
            const float* x1row = x1p + c * WT;
            const ulonglong2 A0 = *reinterpret_cast<const ulonglong2*>(x1row);
            const ulonglong2 A1 = *reinterpret_cast<const ulonglong2*>(x1row + 4);
            const unsigned long long a[4] = {A0.x, A0.y, A1.x, A1.y};

            ulonglong2 X[7];
            const float* bp = xwp + c * SLICE;
            #pragma unroll
            for (int j = 0; j < 7; j++)
                X[j] = *reinterpret_cast<const ulonglong2*>(bp + 4 * j);

            #pragma unroll
            for (int p = 0; p < 11; p++) {
                #pragma unroll
                for (int q = 0; q < 4; q++) {
                    const int k = p + q;                       // 0..13
                    const unsigned long long pk = (k & 1) ? X[k >> 1].y
                                                          : X[k >> 1].x;
                    acc[p][q] = ffma2(a[q], pk, acc[p][q]);
                }
            }
        }

        // ---- per-pi epilogue after last phase ----
        if ((s & 7) == 7) {
            const int pi = wid + ((s >> 3) << 2);
            #pragma unroll
            for (int p = 0; p < 11; p++) {
                if (!(half == 1 && p == 0)) {      // pj=10 duplicated by half A
                    const int pj = half ? (p + 10) : p;
                    float* op = out +
                        (((size_t)b * 441 + pi * 21 + pj) * 32 + h) * 1024 +
                        w0 + 8 * g;
                    float v[8];
                    #pragma unroll
                    for (int q = 0; q < 4; q++) {
                        float2 f = *reinterpret_cast<float2*>(&acc[p][q]);
                        v[2 * q]     = f.x * ((f.x < 0.f) ? sn : sp);
                        v[2 * q + 1] = f.y * ((f.y < 0.f) ? sn : sp);
                    }
                    *reinterpret_cast<float4*>(op) =
                        make_float4(v[0], v[1], v[2], v[3]);
                    *reinterpret_cast<float4*>(op + 4) =
                        make_float4(v[4], v[5], v[6], v[7]);
                }
                #pragma unroll
                for (int q = 0; q < 4; q++) acc[p][q] = 0ull;
            }
        }
        __syncwarp();   // buffer reads done before it is restaged
    }
}

extern "C" void kernel_launch(void* const* d_in, const int* in_sizes, int n_in,
                              void* d_out, int out_size) {
    const float* x1 = (const float*)d_in[0];
    const float* x2 = (const float*)d_in[1];
    float* out = (float*)d_out;

    const size_t smem_bytes =
        (size_t)(32 * WT + 4 * NBUF * CPH * SLICE) * sizeof(float);  // 38912 B
    cudaFuncSetAttribute(corr_kernel,
                         cudaFuncAttributeMaxDynamicSharedMemorySize,
                         (int)smem_bytes);

    dim3 grid(1024 / WT, 32, 4);   // (w-tiles, H, B)
    corr_kernel<<<grid, 128, smem_bytes>>>(x1, x2, out);
}